// round 4
// baseline (speedup 1.0000x reference)
#include <cuda_runtime.h>
#include <cstdint>

// NaiveNeuralGrid: sequential column scan with 3-tap downward row stencil + sin.
//   c'[i] = sin(c[i-2]*w[i-2,j] + c[i-1]*w[i-1,j] + c[i]*w[i,j] + b[i,j])
// Rows partitioned over 64 single-warp CTAs (2 rows/lane). Downward-only
// dependency -> CTAs pipeline with bounded skew via global self-validating
// 64-bit mailboxes (canary = NaN bit pattern, impossible for sin outputs).

#define HGT   4096
#define WID   4096
#define NCTA  64
#define RPC   64          // rows per CTA (32 lanes * 2 rows)
#define CHUNK 8

#define CANARY 0x7ff8dead7ff8deadULL

// mbox[c][s]: for s>=1, packed (c[64c-2], c[64c-1]) AFTER step s-1 (written by CTA c-1).
// s==0 holds the initial (x-derived) values. CTA 0's mailbox is all zeros
// (zero boundary condition). +8 pad keeps the final write (slot 4096) in bounds.
__device__ unsigned long long g_mbox[NCTA][WID + 8];

static __device__ __forceinline__ unsigned long long ldg_rlx(const unsigned long long* p) {
    unsigned long long v;
    asm volatile("ld.global.relaxed.gpu.b64 %0, [%1];" : "=l"(v) : "l"(p));
    return v;
}
static __device__ __forceinline__ void stg_rlx(unsigned long long* p, unsigned long long v) {
    asm volatile("st.global.relaxed.gpu.b64 [%0], %1;" :: "l"(p), "l"(v));
}

__global__ void ng_init_kernel(const float* __restrict__ x) {
    int idx = blockIdx.x * blockDim.x + threadIdx.x;
    const int total = NCTA * (WID + 8);
    if (idx >= total) return;
    int c = idx / (WID + 8);
    int s = idx % (WID + 8);
    unsigned long long v;
    if (c == 0) {
        v = 0ULL;                                  // zero boundary for rows -1, -2
    } else if (s == 0) {
        unsigned lo = __float_as_uint(x[RPC * c - 2]);   // c[base-2] initial
        unsigned hi = __float_as_uint(x[RPC * c - 1]);   // c[base-1] initial
        v = ((unsigned long long)hi << 32) | lo;
    } else {
        v = CANARY;
    }
    g_mbox[c][s] = v;
}

__global__ void __launch_bounds__(32, 1) ng_scan_kernel(
    const float* __restrict__ x,
    const float* __restrict__ w,
    const float* __restrict__ b,
    float* __restrict__ out)
{
    const int c  = blockIdx.x;
    const int k  = threadIdx.x;
    const int rA = c * RPC + 2 * k;     // even row owned by this lane
    // row rB = rA + 1

    // Weight/bias streams. Rows rA-1, rA-2 are duplicate-loaded (owned by the
    // lane/CTA below; L1 catches the reuse). Clamp for global rows 0/1: the
    // corresponding carries are forced to 0 so the values are never used.
    const float* wA  = w + (size_t)rA * WID;
    const float* wB  = wA + WID;
    const float* wm1 = w + (size_t)(rA >= 1 ? rA - 1 : 0) * WID;
    const float* wm2 = w + (size_t)(rA >= 2 ? rA - 2 : 0) * WID;
    const float* bA  = b + (size_t)rA * WID;
    const float* bB  = bA + WID;

    float cA = x[rA];
    float cB = x[rA + 1];

    const unsigned long long* mb_in  = g_mbox[c];
    unsigned long long*       mb_out = g_mbox[(c + 1 < NCTA) ? c + 1 : c];
    const bool writer = (k == 31) && (c + 1 < NCTA);
    const bool lane0  = (k == 0);

    // Prime mailbox chunk: slots 0..CHUNK-1 (slot j feeds step j).
    unsigned long long cur[CHUNK];
#pragma unroll
    for (int t = 0; t < CHUNK; ++t) {
        unsigned long long v = ldg_rlx(mb_in + t);
        while (v == CANARY) v = ldg_rlx(mb_in + t);
        cur[t] = v;
    }

    for (int J = 0; J < WID; J += CHUNK) {
        // Optimistic prefetch of next mailbox chunk (validated at chunk end).
        unsigned long long nxt[CHUNK];
        const bool more = (J + CHUNK) < WID;
        if (more) {
#pragma unroll
            for (int t = 0; t < CHUNK; ++t)
                nxt[t] = ldg_rlx(mb_in + (J + CHUNK) + t);
        }

        // Stream 8 steps of weights/bias (two float4 groups per stream).
        const int g = J >> 2;
        float4 q;
        float m2[CHUNK], m1[CHUNK], a0[CHUNK], b0[CHUNK], pA[CHUNK], pB[CHUNK];
        q = ((const float4*)wm2)[g];   m2[0]=q.x; m2[1]=q.y; m2[2]=q.z; m2[3]=q.w;
        q = ((const float4*)wm2)[g+1]; m2[4]=q.x; m2[5]=q.y; m2[6]=q.z; m2[7]=q.w;
        q = ((const float4*)wm1)[g];   m1[0]=q.x; m1[1]=q.y; m1[2]=q.z; m1[3]=q.w;
        q = ((const float4*)wm1)[g+1]; m1[4]=q.x; m1[5]=q.y; m1[6]=q.z; m1[7]=q.w;
        q = ((const float4*)wA )[g];   a0[0]=q.x; a0[1]=q.y; a0[2]=q.z; a0[3]=q.w;
        q = ((const float4*)wA )[g+1]; a0[4]=q.x; a0[5]=q.y; a0[6]=q.z; a0[7]=q.w;
        q = ((const float4*)wB )[g];   b0[0]=q.x; b0[1]=q.y; b0[2]=q.z; b0[3]=q.w;
        q = ((const float4*)wB )[g+1]; b0[4]=q.x; b0[5]=q.y; b0[6]=q.z; b0[7]=q.w;
        q = ((const float4*)bA )[g];   pA[0]=q.x; pA[1]=q.y; pA[2]=q.z; pA[3]=q.w;
        q = ((const float4*)bA )[g+1]; pA[4]=q.x; pA[5]=q.y; pA[6]=q.z; pA[7]=q.w;
        q = ((const float4*)bB )[g];   pB[0]=q.x; pB[1]=q.y; pB[2]=q.z; pB[3]=q.w;
        q = ((const float4*)bB )[g+1]; pB[4]=q.x; pB[5]=q.y; pB[6]=q.z; pB[7]=q.w;

#pragma unroll
        for (int t = 0; t < CHUNK; ++t) {
            // Neighbor carries (previous step's state of rows rA-2, rA-1).
            float cm2 = __shfl_up_sync(0xffffffffu, cA, 1);
            float cm1 = __shfl_up_sync(0xffffffffu, cB, 1);
            if (lane0) {
                cm2 = __uint_as_float((unsigned)(cur[t] & 0xffffffffu));
                cm1 = __uint_as_float((unsigned)(cur[t] >> 32));
            }
            float zA = fmaf(cA, a0[t], fmaf(cm1, m1[t], fmaf(cm2, m2[t], pA[t])));
            float zB = fmaf(cB, b0[t], fmaf(cA, a0[t], fmaf(cm1, m1[t], pB[t])));
            cA = __sinf(zA);
            cB = __sinf(zB);
            if (writer) {
                unsigned long long v =
                    ((unsigned long long)__float_as_uint(cB) << 32) |
                    (unsigned long long)__float_as_uint(cA);
                stg_rlx(mb_out + (J + t + 1), v);
            }
        }

        if (more) {
#pragma unroll
            for (int t = 0; t < CHUNK; ++t) {
                unsigned long long v = nxt[t];
                while (v == CANARY) v = ldg_rlx(mb_in + (J + CHUNK) + t);
                cur[t] = v;
            }
        }
    }

    out[rA]     = cA;
    out[rA + 1] = cB;
}

extern "C" void kernel_launch(void* const* d_in, const int* in_sizes, int n_in,
                              void* d_out, int out_size) {
    (void)in_sizes; (void)n_in; (void)out_size;
    const float* x = (const float*)d_in[0];
    const float* w = (const float*)d_in[1];
    const float* b = (const float*)d_in[2];
    float* out = (float*)d_out;

    const int total = NCTA * (WID + 8);
    ng_init_kernel<<<(total + 255) / 256, 256>>>(x);
    ng_scan_kernel<<<NCTA, 32>>>(x, w, b, out);
}

// round 5
// speedup vs baseline: 1.4734x; 1.4734x over previous
#include <cuda_runtime.h>
#include <cstdint>

// NaiveNeuralGrid: sequential column scan with 3-tap downward row stencil + sin.
//   c'[i] = sin(c[i-2]*w[i-2,j] + c[i-1]*w[i-1,j] + c[i]*w[i,j] + b[i,j])
// 64 single-warp CTAs, 2 rows/lane, carries in registers. Cross-CTA pipeline
// via global self-validating 64-bit mailboxes (NaN canary; sin outputs are
// always in [-1,1] so they can never alias it).
//
// R4 changes vs R3 (842us):
//  - double-buffered register prefetch of next chunk's weight/bias streams
//  - wm1/wm2 streams replaced by shfl_up of a0/b0 (lane0 keeps a tiny halo load)
//  - balanced FMA tree to shorten the post-shfl dependency depth

#define WID   4096
#define NCTA  64
#define RPC   64          // rows per CTA (32 lanes * 2 rows)
#define CHUNK 8
#define CANARY 0x7ff8dead7ff8deadULL

__device__ unsigned long long g_mbox[NCTA][WID + 8];

static __device__ __forceinline__ unsigned long long ldg_rlx(const unsigned long long* p) {
    unsigned long long v;
    asm volatile("ld.global.relaxed.gpu.b64 %0, [%1];" : "=l"(v) : "l"(p));
    return v;
}
static __device__ __forceinline__ void stg_rlx(unsigned long long* p, unsigned long long v) {
    asm volatile("st.global.relaxed.gpu.b64 [%0], %1;" :: "l"(p), "l"(v));
}

__global__ void ng_init_kernel(const float* __restrict__ x) {
    int idx = blockIdx.x * blockDim.x + threadIdx.x;
    const int total = NCTA * (WID + 8);
    if (idx >= total) return;
    int c = idx / (WID + 8);
    int s = idx % (WID + 8);
    unsigned long long v;
    if (c == 0) {
        v = 0ULL;                                  // zero boundary rows -1, -2
    } else if (s == 0) {
        unsigned lo = __float_as_uint(x[RPC * c - 2]);
        unsigned hi = __float_as_uint(x[RPC * c - 1]);
        v = ((unsigned long long)hi << 32) | lo;
    } else {
        v = CANARY;
    }
    g_mbox[c][s] = v;
}

__global__ void __launch_bounds__(32, 1) ng_scan_kernel(
    const float* __restrict__ x,
    const float* __restrict__ w,
    const float* __restrict__ b,
    float* __restrict__ out)
{
    const int c  = blockIdx.x;
    const int k  = threadIdx.x;
    const int rA = c * RPC + 2 * k;          // even row owned by this lane

    const float* wA = w + (size_t)rA * WID;
    const float* wB = wA + WID;
    const float* bA = b + (size_t)rA * WID;
    const float* bB = bA + WID;

    const bool lane0 = (k == 0);
    // Halo weight rows (rA-1, rA-2) are only real for lane0 (they belong to the
    // CTA below); other lanes alias wA so the loads are L1-hit duplicates and
    // the warp stays convergent.
    const int r1 = (rA >= 1) ? rA - 1 : 0;
    const int r2 = (rA >= 2) ? rA - 2 : 0;
    const float* hp1 = lane0 ? (w + (size_t)r1 * WID) : wA;
    const float* hp2 = lane0 ? (w + (size_t)r2 * WID) : wA;

    float cA = x[rA];
    float cB = x[rA + 1];

    const unsigned long long* mb_in  = g_mbox[c];
    unsigned long long*       mb_out = g_mbox[(c + 1 < NCTA) ? (c + 1) : c];
    const bool writer = (k == 31) && (c + 1 < NCTA);

    // Prime mailbox slots 0..CHUNK-1 (slot j feeds step j).
    unsigned long long cur[CHUNK], nxt[CHUNK];
#pragma unroll
    for (int t = 0; t < CHUNK; ++t) {
        unsigned long long v = ldg_rlx(mb_in + t);
        while (v == CANARY) v = ldg_rlx(mb_in + t);
        cur[t] = v;
    }

    // Double-buffered register streams.
    float Xa[CHUNK], Xb[CHUNK], Xpa[CHUNK], Xpb[CHUNK], Xh1[CHUNK], Xh2[CHUNK];
    float Ya[CHUNK], Yb[CHUNK], Ypa[CHUNK], Ypb[CHUNK], Yh1[CHUNK], Yh2[CHUNK];
    float m1[CHUNK], m2[CHUNK];

#define LD8(dst, ptr, g) do { \
    float4 q0_ = ((const float4*)(ptr))[(g)]; \
    float4 q1_ = ((const float4*)(ptr))[(g) + 1]; \
    dst[0]=q0_.x; dst[1]=q0_.y; dst[2]=q0_.z; dst[3]=q0_.w; \
    dst[4]=q1_.x; dst[5]=q1_.y; dst[6]=q1_.z; dst[7]=q1_.w; } while(0)

#define LOADW(g, A0,B0,PA,PB,H1,H2) do { \
    LD8(A0, wA,  g); LD8(B0, wB,  g); \
    LD8(PA, bA,  g); LD8(PB, bB,  g); \
    LD8(H1, hp1, g); LD8(H2, hp2, g); } while(0)

#define PROCESS(Jb, A0,B0,PA,PB,H1,H2, NA,NB,NPA,NPB,NH1,NH2) do { \
    const int  Jn_   = (Jb) + CHUNK; \
    const bool more_ = (Jn_ < WID); \
    /* prefetch: next mailbox chunk + next weight chunk, consumed ~480cyc later */ \
    if (more_) { \
        _Pragma("unroll") \
        for (int t = 0; t < CHUNK; ++t) nxt[t] = ldg_rlx(mb_in + Jn_ + t); \
        LOADW(Jn_ >> 2, NA, NB, NPA, NPB, NH1, NH2); \
    } \
    /* weights of rows rA-1, rA-2 = lane k-1's b0/a0 streams (off-chain) */ \
    _Pragma("unroll") \
    for (int t = 0; t < CHUNK; ++t) { \
        float s2_ = __shfl_up_sync(0xffffffffu, A0[t], 1); \
        float s1_ = __shfl_up_sync(0xffffffffu, B0[t], 1); \
        m2[t] = lane0 ? H2[t] : s2_; \
        m1[t] = lane0 ? H1[t] : s1_; \
    } \
    _Pragma("unroll") \
    for (int t = 0; t < CHUNK; ++t) { \
        float u2_ = __shfl_up_sync(0xffffffffu, cA, 1); \
        float u1_ = __shfl_up_sync(0xffffffffu, cB, 1); \
        float cm2_ = lane0 ? __uint_as_float((unsigned)(cur[t] & 0xffffffffu)) : u2_; \
        float cm1_ = lane0 ? __uint_as_float((unsigned)(cur[t] >> 32))         : u1_; \
        /* sA_/sB_ depend only on local prev state -> computed during the shfl */ \
        float sA_ = fmaf(cA, A0[t], PA[t]); \
        float sB_ = fmaf(cA, A0[t], fmaf(cB, B0[t], PB[t])); \
        float zA_ = fmaf(cm1_, m1[t], fmaf(cm2_, m2[t], sA_)); \
        float zB_ = fmaf(cm1_, m1[t], sB_); \
        cA = __sinf(zA_); \
        cB = __sinf(zB_); \
        if (writer) { \
            unsigned long long v_ = ((unsigned long long)__float_as_uint(cB) << 32) \
                                  | (unsigned long long)__float_as_uint(cA); \
            stg_rlx(mb_out + (Jb) + t + 1, v_); \
        } \
    } \
    /* validate the optimistic mailbox prefetch */ \
    if (more_) { \
        _Pragma("unroll") \
        for (int t = 0; t < CHUNK; ++t) { \
            unsigned long long v_ = nxt[t]; \
            while (v_ == CANARY) v_ = ldg_rlx(mb_in + Jn_ + t); \
            cur[t] = v_; \
        } \
    } } while(0)

    // Prologue: fill X buffers with chunk 0.
    LOADW(0, Xa, Xb, Xpa, Xpb, Xh1, Xh2);

#pragma unroll 1
    for (int J = 0; J < WID; J += 2 * CHUNK) {
        PROCESS(J,         Xa,Xb,Xpa,Xpb,Xh1,Xh2,  Ya,Yb,Ypa,Ypb,Yh1,Yh2);
        PROCESS(J + CHUNK, Ya,Yb,Ypa,Ypb,Yh1,Yh2,  Xa,Xb,Xpa,Xpb,Xh1,Xh2);
    }

    out[rA]     = cA;
    out[rA + 1] = cB;
}

extern "C" void kernel_launch(void* const* d_in, const int* in_sizes, int n_in,
                              void* d_out, int out_size) {
    (void)in_sizes; (void)n_in; (void)out_size;
    const float* x = (const float*)d_in[0];
    const float* w = (const float*)d_in[1];
    const float* b = (const float*)d_in[2];
    float* out = (float*)d_out;

    const int total = NCTA * (WID + 8);
    ng_init_kernel<<<(total + 255) / 256, 256>>>(x);
    ng_scan_kernel<<<NCTA, 32>>>(x, w, b, out);
}

// round 6
// speedup vs baseline: 1.5684x; 1.0645x over previous
#include <cuda_runtime.h>
#include <cstdint>

// NaiveNeuralGrid: sequential column scan with 3-tap downward row stencil + sin.
//   c'[i] = sin(c[i-2]*w[i-2,j] + c[i-1]*w[i-1,j] + c[i]*w[i,j] + b[i,j])
// 64 single-warp CTAs, 2 rows/lane, carries in registers. Cross-CTA pipeline
// via global self-validating 64-bit mailboxes (NaN canary; sin outputs are in
// [-1,1] so they can never alias it).
//
// R5 vs R4 (572us): weight/bias transport moved to a 6-stage cp.async->SMEM
// ring (5 chunks of prefetch depth, no register writeback on loads). LDS
// consumes a chunk deposited ~2400 cycles earlier -> DRAM latency off-chain.

#define WID    4096
#define NCTA   64
#define RPC    64           // rows per CTA (32 lanes * 2 rows)
#define CHUNK  8
#define NCHUNK (WID / CHUNK)
#define STAGES 6
#define NSTRM  6            // a0, b0, pA, pB, h1, h2
#define CANARY 0x7ff8dead7ff8deadULL

__device__ unsigned long long g_mbox[NCTA][WID + 8];

static __device__ __forceinline__ unsigned long long ldg_rlx(const unsigned long long* p) {
    unsigned long long v;
    asm volatile("ld.global.relaxed.gpu.b64 %0, [%1];" : "=l"(v) : "l"(p));
    return v;
}
static __device__ __forceinline__ void stg_rlx(unsigned long long* p, unsigned long long v) {
    asm volatile("st.global.relaxed.gpu.b64 [%0], %1;" :: "l"(p), "l"(v));
}
static __device__ __forceinline__ void cpasync16(uint32_t dst, const float* src) {
    asm volatile("cp.async.cg.shared.global [%0], [%1], 16;" :: "r"(dst), "l"(src) : "memory");
}

__global__ void ng_init_kernel(const float* __restrict__ x) {
    int idx = blockIdx.x * blockDim.x + threadIdx.x;
    const int total = NCTA * (WID + 8);
    if (idx >= total) return;
    int c = idx / (WID + 8);
    int s = idx % (WID + 8);
    unsigned long long v;
    if (c == 0) {
        v = 0ULL;                                  // zero boundary rows -1, -2
    } else if (s == 0) {
        unsigned lo = __float_as_uint(x[RPC * c - 2]);
        unsigned hi = __float_as_uint(x[RPC * c - 1]);
        v = ((unsigned long long)hi << 32) | lo;
    } else {
        v = CANARY;
    }
    g_mbox[c][s] = v;
}

__global__ void __launch_bounds__(32, 1) ng_scan_kernel(
    const float* __restrict__ x,
    const float* __restrict__ w,
    const float* __restrict__ b,
    float* __restrict__ out)
{
    // ring[stage][stream][lane][8 floats]; lane stride 32B, stream stride 1KB.
    __shared__ float ring[STAGES * NSTRM * 32 * 8];

    const int c  = blockIdx.x;
    const int k  = threadIdx.x;
    const int rA = c * RPC + 2 * k;          // even row owned by this lane

    const float* wA = w + (size_t)rA * WID;
    const float* wB = wA + WID;
    const float* bA = b + (size_t)rA * WID;
    const float* bB = bA + WID;

    const bool lane0 = (k == 0);
    // Real halo rows only for lane0 (they belong to the CTA below); other
    // lanes alias wA so the warp stays convergent (values unused there).
    const int r1 = (rA >= 1) ? rA - 1 : 0;
    const int r2 = (rA >= 2) ? rA - 2 : 0;
    const float* hp1 = lane0 ? (w + (size_t)r1 * WID) : wA;
    const float* hp2 = lane0 ? (w + (size_t)r2 * WID) : wA;

    const float* src[NSTRM] = { wA, wB, bA, bB, hp1, hp2 };

    const uint32_t smem_base = (uint32_t)__cvta_generic_to_shared(ring);

    float cA = x[rA];
    float cB = x[rA + 1];

    const unsigned long long* mb_in  = g_mbox[c];
    unsigned long long*       mb_out = g_mbox[(c + 1 < NCTA) ? (c + 1) : c];
    const bool writer = (k == 31) && (c + 1 < NCTA);

    // ---- async-copy ring: issue one chunk (8 columns of all 6 streams) ----
#define ISSUE_CHUNK(Jc) do {                                                  \
        int st_ = (Jc) % STAGES;                                              \
        _Pragma("unroll")                                                     \
        for (int s_ = 0; s_ < NSTRM; ++s_) {                                  \
            uint32_t d_ = smem_base + (uint32_t)(((st_ * NSTRM + s_) * 32 + k) * 32); \
            const float* g_ = src[s_] + (Jc) * CHUNK;                         \
            cpasync16(d_, g_);                                                \
            cpasync16(d_ + 16, g_ + 4);                                       \
        }                                                                     \
        asm volatile("cp.async.commit_group;" ::: "memory");                  \
    } while (0)

    // Prologue: fill stages 0..STAGES-2 (5 groups in flight).
#pragma unroll
    for (int p = 0; p < STAGES - 1; ++p) ISSUE_CHUNK(p);

    // Prime mailbox slots 0..CHUNK-1 (slot j feeds step j).
    unsigned long long cur[CHUNK], nxt[CHUNK];
#pragma unroll
    for (int t = 0; t < CHUNK; ++t) {
        unsigned long long v = ldg_rlx(mb_in + t);
        while (v == CANARY) v = ldg_rlx(mb_in + t);
        cur[t] = v;
    }

    float a0[CHUNK], b0[CHUNK], pA[CHUNK], pB[CHUNK], h1[CHUNK], h2[CHUNK];
    float m1[CHUNK], m2[CHUNK];

#pragma unroll 1
    for (int J = 0; J < NCHUNK; ++J) {
        const bool more = (J + 1) < NCHUNK;

        // Optimistic prefetch of next mailbox chunk (validated after compute).
        if (more) {
#pragma unroll
            for (int t = 0; t < CHUNK; ++t)
                nxt[t] = ldg_rlx(mb_in + (J + 1) * CHUNK + t);
        }

        // Oldest in-flight chunk (J) is complete once <= STAGES-2 groups pend.
        asm volatile("cp.async.wait_group %0;" :: "n"(STAGES - 2) : "memory");

        // LDS this chunk's streams into registers (lat 29, off the chain).
        {
            const int st = J % STAGES;
            const float4* p4 = (const float4*)(ring + (size_t)(st * NSTRM * 32 * 8) + k * 8);
            float4 q0, q1;
#define PULL(dst, sidx) \
            q0 = p4[(sidx) * 64 + 0]; q1 = p4[(sidx) * 64 + 1]; \
            dst[0]=q0.x; dst[1]=q0.y; dst[2]=q0.z; dst[3]=q0.w; \
            dst[4]=q1.x; dst[5]=q1.y; dst[6]=q1.z; dst[7]=q1.w;
            PULL(a0, 0) PULL(b0, 1) PULL(pA, 2) PULL(pB, 3) PULL(h1, 4) PULL(h2, 5)
#undef PULL
        }

        // Weights of rows rA-1, rA-2 = lane k-1's b0/a0 streams (off-chain).
#pragma unroll
        for (int t = 0; t < CHUNK; ++t) {
            float s2 = __shfl_up_sync(0xffffffffu, a0[t], 1);
            float s1 = __shfl_up_sync(0xffffffffu, b0[t], 1);
            m2[t] = lane0 ? h2[t] : s2;
            m1[t] = lane0 ? h1[t] : s1;
        }

#pragma unroll
        for (int t = 0; t < CHUNK; ++t) {
            float u2 = __shfl_up_sync(0xffffffffu, cA, 1);
            float u1 = __shfl_up_sync(0xffffffffu, cB, 1);
            float cm2 = lane0 ? __uint_as_float((unsigned)(cur[t] & 0xffffffffu)) : u2;
            float cm1 = lane0 ? __uint_as_float((unsigned)(cur[t] >> 32))         : u1;
            // sA/sB depend only on local prev state -> computed during the shfl.
            float sA = fmaf(cA, a0[t], pA[t]);
            float sB = fmaf(cA, a0[t], fmaf(cB, b0[t], pB[t]));
            float zA = fmaf(cm1, m1[t], fmaf(cm2, m2[t], sA));
            float zB = fmaf(cm1, m1[t], sB);
            cA = __sinf(zA);
            cB = __sinf(zB);
            if (writer) {
                unsigned long long v =
                    ((unsigned long long)__float_as_uint(cB) << 32) |
                    (unsigned long long)__float_as_uint(cA);
                stg_rlx(mb_out + J * CHUNK + t + 1, v);
            }
        }

        // Validate the optimistic mailbox prefetch.
        if (more) {
#pragma unroll
            for (int t = 0; t < CHUNK; ++t) {
                unsigned long long v = nxt[t];
                while (v == CANARY) v = ldg_rlx(mb_in + (J + 1) * CHUNK + t);
                cur[t] = v;
            }
        }

        // Refill the stage consumed last iteration with chunk J+STAGES-1.
        if (J + STAGES - 1 < NCHUNK) ISSUE_CHUNK(J + STAGES - 1);
    }

    out[rA]     = cA;
    out[rA + 1] = cB;
}

extern "C" void kernel_launch(void* const* d_in, const int* in_sizes, int n_in,
                              void* d_out, int out_size) {
    (void)in_sizes; (void)n_in; (void)out_size;
    const float* x = (const float*)d_in[0];
    const float* w = (const float*)d_in[1];
    const float* b = (const float*)d_in[2];
    float* out = (float*)d_out;

    const int total = NCTA * (WID + 8);
    ng_init_kernel<<<(total + 255) / 256, 256>>>(x);
    ng_scan_kernel<<<NCTA, 32>>>(x, w, b, out);
}